// round 13
// baseline (speedup 1.0000x reference)
#include <cuda_runtime.h>
#include <cuda_fp16.h>
#include <cstdint>

// Problem constants
#define BB 4
#define VV 256
#define HH 128
constexpr int ROWS_H = BB * VV;           // 1024
constexpr int ROWS_E = BB * VV * VV;      // 262144
constexpr int TM     = 128;               // e-rows per block in k_main
constexpr int NBLK2  = ROWS_E / TM;       // 2048 (stat row-blocks)
constexpr int GRID_MAIN = NBLK2 * 2;      // 4096 (N split in halves)
constexpr float EPS  = 1e-5f;
constexpr float LO_SCALE   = 2048.f;
constexpr float LO_UNSCALE = 1.f / 2048.f;

// ---------------- smem geometry for k_main ----------------
constexpr int LDC    = 72;                  // fp16 elems per tile row (144 B; 9 units, odd)
constexpr int A_TILE = 128 * LDC * 2;       // 18432 B (128 rows x 64 K fp16)
constexpr int B_TILE = 64 * LDC * 2;        // 9216 B  (64 N x 64 K fp16)
constexpr int LDSG   = 68;                  // f32 stage row stride (odd 16B-units)
constexpr int SM_C2  = 0;                   // 64 floats (+pad)
constexpr int SM_AHI = 1024;
constexpr int SM_ALO = SM_AHI + A_TILE;     // 19456
constexpr int SM_BW0 = SM_ALO + A_TILE;     // 37888
constexpr int SM_BW1 = SM_BW0 + B_TILE;     // 47104
constexpr int SM_STG = SM_BW1 + B_TILE;     // 56320 (128 x 68 f32 = 34816)
constexpr int SM_RED = SM_STG + 128 * LDSG * 4;  // 91136 (3 x 256 floats)
constexpr int SM_TOTAL = SM_RED + 3072;     // 94208 -> 2 CTAs/SM

// Scratch
__device__ float g_enew[(size_t)ROWS_E * HH];   // 134 MB
__device__ float g_lin[4 * ROWS_H * HH];        // Uh,Vh,Ah,Bh
__device__ __align__(16) char g_bt[4 * B_TILE]; // pre-converted Cw fp16 [nh][ch]
__device__ float g_statS[HH * NBLK2];
__device__ float g_statQ[HH * NBLK2];
__device__ float g_aggp[HH * NBLK2];
__device__ float g_hnew[ROWS_H * HH];
__device__ float g_scaleE[HH];
__device__ float g_shiftE[HH];

__device__ __forceinline__ uint32_t smem_u32(const void* p) {
    uint32_t a;
    asm("{ .reg .u64 t; cvta.to.shared.u64 t, %1; cvt.u32.u64 %0, t; }" : "=r"(a) : "l"(p));
    return a;
}
__device__ __forceinline__ void ldmatrix_x4(uint32_t& r0, uint32_t& r1, uint32_t& r2, uint32_t& r3, uint32_t addr) {
    asm volatile("ldmatrix.sync.aligned.m8n8.x4.shared.b16 {%0,%1,%2,%3}, [%4];"
        : "=r"(r0), "=r"(r1), "=r"(r2), "=r"(r3) : "r"(addr) : "memory");
}
__device__ __forceinline__ void mma_f32(float (&d)[4], const uint32_t (&a)[4], uint32_t b0, uint32_t b1) {
    asm("mma.sync.aligned.m16n8k16.row.col.f32.f16.f16.f32 "
        "{%0,%1,%2,%3}, {%4,%5,%6,%7}, {%8,%9}, {%0,%1,%2,%3};"
        : "+f"(d[0]), "+f"(d[1]), "+f"(d[2]), "+f"(d[3])
        : "r"(a[0]), "r"(a[1]), "r"(a[2]), "r"(a[3]), "r"(b0), "r"(b1));
}
__device__ __forceinline__ void mma_f16acc(uint32_t (&d)[2], const uint32_t (&a)[4], uint32_t b0, uint32_t b1) {
    asm("mma.sync.aligned.m16n8k16.row.col.f16.f16.f16.f16 "
        "{%0,%1}, {%2,%3,%4,%5}, {%6,%7}, {%0,%1};"
        : "+r"(d[0]), "+r"(d[1])
        : "r"(a[0]), "r"(a[1]), "r"(a[2]), "r"(a[3]), "r"(b0), "r"(b1));
}
__device__ __forceinline__ void cp_async16(uint32_t smem_dst, const void* gmem_src) {
    asm volatile("cp.async.cg.shared.global [%0], [%1], 16;" :: "r"(smem_dst), "l"(gmem_src) : "memory");
}
#define CP_COMMIT() asm volatile("cp.async.commit_group;" ::: "memory")
#define CP_WAIT(n)  asm volatile("cp.async.wait_group %0;" :: "n"(n) : "memory")

// A conversion: hi = fp16(v), lo = fp16(2048*(v - hi))
__device__ __forceinline__ void cvtA_store4(float4 v, char* smem, uint32_t hiOff, uint32_t loOff) {
    __half h0 = __float2half_rn(v.x), h1 = __float2half_rn(v.y);
    __half h2 = __float2half_rn(v.z), h3 = __float2half_rn(v.w);
    __half l0 = __float2half_rn(LO_SCALE * (v.x - __half2float(h0)));
    __half l1 = __float2half_rn(LO_SCALE * (v.y - __half2float(h1)));
    __half l2 = __float2half_rn(LO_SCALE * (v.z - __half2float(h2)));
    __half l3 = __float2half_rn(LO_SCALE * (v.w - __half2float(h3)));
    uint2 uh, ul;
    uh.x = ((uint32_t)__half_as_ushort(h1) << 16) | __half_as_ushort(h0);
    uh.y = ((uint32_t)__half_as_ushort(h3) << 16) | __half_as_ushort(h2);
    ul.x = ((uint32_t)__half_as_ushort(l1) << 16) | __half_as_ushort(l0);
    ul.y = ((uint32_t)__half_as_ushort(l3) << 16) | __half_as_ushort(l2);
    *(uint2*)(smem + hiOff) = uh;
    *(uint2*)(smem + loOff) = ul;
}
__device__ __forceinline__ void cvtB_store4(float4 v, char* smem, uint32_t off) {
    __half h0 = __float2half_rn(v.x), h1 = __float2half_rn(v.y);
    __half h2 = __float2half_rn(v.z), h3 = __float2half_rn(v.w);
    uint2 u;
    u.x = ((uint32_t)__half_as_ushort(h1) << 16) | __half_as_ushort(h0);
    u.y = ((uint32_t)__half_as_ushort(h3) << 16) | __half_as_ushort(h2);
    *(uint2*)(smem + off) = u;
}

// ---------------- K1: HMMA Ce GEMM (fp16 hi-f32acc + lo-f16acc) ----------------
__global__ void __launch_bounds__(256, 2)
k_main(const float* __restrict__ e, const float* __restrict__ Cb) {
    extern __shared__ char sm[];
    uint32_t smb = smem_u32(sm);
    int tid = threadIdx.x;
    int wid = tid >> 5, lane = tid & 31;

    int blk = blockIdx.x;
    int rowblk = blk >> 1;        // 0..2047 (stat index)
    int nh  = blk & 1;            // N half
    int n0  = nh * 64;
    int rbase = rowblk * TM;
    int bi = rowblk >> 1;         // b*V + i
    int b  = bi >> 8;
    int j0 = (rowblk & 1) * TM;   // j range start

    // c2 = Cb + Bh[bi], this block's 64 columns
    if (tid < 64)
        ((float*)(sm + SM_C2))[tid] = Cb[n0 + tid] + g_lin[(size_t)3 * ROWS_H * HH + (size_t)bi * HH + n0 + tid];

    // group 1: both B chunk tiles
    {
        const char* bsrc = g_bt + (size_t)nh * 2 * B_TILE;
        for (int i = tid; i < 2 * B_TILE / 16; i += 256)
            cp_async16(smb + SM_BW0 + i * 16, bsrc + i * 16);
    }
    CP_COMMIT();
    // group 2: stage chunk-1 A (f32) for later convert
    {
        const float* eb1 = e + (size_t)rbase * HH + 64;
        for (int i = tid; i < 128 * 16; i += 256) {
            int row = i >> 4, seg = i & 15;
            cp_async16(smb + SM_STG + (uint32_t)(row * LDSG + seg * 4) * 4,
                       eb1 + (size_t)row * HH + seg * 4);
        }
    }
    CP_COMMIT();

    // chunk-0 A: direct load + convert
    {
        const float* eb = e + (size_t)rbase * HH;
        for (int idx = tid; idx < 128 * 16; idx += 256) {
            int row = idx >> 4, c4 = idx & 15;
            uint32_t off = (uint32_t)row * (LDC * 2) + c4 * 8;
            float4 ev = *(const float4*)&eb[(size_t)row * HH + c4 * 4];
            cvtA_store4(ev, sm, SM_AHI + off, SM_ALO + off);
        }
    }

    int wm = wid >> 1, wn = wid & 1;      // 4 x 2 warp grid; warp tile 32x32
    float    d[2][4][4];
    uint32_t dl[2][4][2];
#pragma unroll
    for (int mt = 0; mt < 2; mt++)
#pragma unroll
        for (int nt = 0; nt < 4; nt++) {
#pragma unroll
            for (int q = 0; q < 4; q++) d[mt][nt][q] = 0.f;
            dl[mt][nt][0] = 0u; dl[mt][nt][1] = 0u;
        }

    uint32_t aLaneOff = (uint32_t)(wm * 32 + (lane & 15)) * (LDC * 2) + (lane >> 4) * 16;
    uint32_t bLaneOff = (uint32_t)(wn * 32 + (((lane >> 4) & 1) * 8) + (lane & 7)) * (LDC * 2)
                      + ((lane >> 3) & 1) * 16;

#pragma unroll
    for (int ch = 0; ch < 2; ch++) {
        if (ch == 0) { CP_WAIT(1); }      // B tiles ready; stage may be in flight
        __syncthreads();

        uint32_t aHiBase = smb + SM_AHI + aLaneOff;
        uint32_t aLoBase = smb + SM_ALO + aLaneOff;
        uint32_t bBase   = smb + (ch ? SM_BW1 : SM_BW0) + bLaneOff;
#pragma unroll
        for (int kk = 0; kk < 4; kk++) {
            uint32_t bb[8];
            ldmatrix_x4(bb[0], bb[1], bb[2], bb[3], bBase + kk * 32);
            ldmatrix_x4(bb[4], bb[5], bb[6], bb[7], bBase + kk * 32 + 16 * (LDC * 2));
            uint32_t a0[4], a1[4], c0[4], c1[4];
            ldmatrix_x4(a0[0], a0[1], a0[2], a0[3], aHiBase + kk * 32);
            ldmatrix_x4(a1[0], a1[1], a1[2], a1[3], aHiBase + kk * 32 + 16 * (LDC * 2));
            ldmatrix_x4(c0[0], c0[1], c0[2], c0[3], aLoBase + kk * 32);
            ldmatrix_x4(c1[0], c1[1], c1[2], c1[3], aLoBase + kk * 32 + 16 * (LDC * 2));
#pragma unroll
            for (int nt = 0; nt < 4; nt++) {
                uint32_t b0 = bb[(nt >> 1) * 4 + (nt & 1) * 2];
                uint32_t b1 = bb[(nt >> 1) * 4 + (nt & 1) * 2 + 1];
                mma_f32(d[0][nt], a0, b0, b1);
                mma_f32(d[1][nt], a1, b0, b1);
                mma_f16acc(dl[0][nt], c0, b0, b1);
                mma_f16acc(dl[1][nt], c1, b0, b1);
            }
        }
        __syncthreads();   // A tiles consumed
        if (ch == 0) {
            CP_WAIT(0);    // stage ready
            const float* stg = (const float*)(sm + SM_STG);
            for (int idx = tid; idx < 128 * 16; idx += 256) {
                int row = idx >> 4, c4 = idx & 15;
                uint32_t off = (uint32_t)row * (LDC * 2) + c4 * 8;
                float4 ev = *(const float4*)&stg[row * LDSG + c4 * 4];
                cvtA_store4(ev, sm, SM_AHI + off, SM_ALO + off);
            }
        }
    }

    // -------- fragment-direct epilogue --------
    {
        int g = lane >> 2, t2 = (lane & 3) * 2;
        const float* c2s = (const float*)(sm + SM_C2);
        const float* ahB = g_lin + (size_t)2 * ROWS_H * HH + (size_t)(b * VV + j0) * HH;
        const float* vhB = g_lin + (size_t)1 * ROWS_H * HH + (size_t)(b * VV + j0) * HH;
        float* enB = g_enew + (size_t)rbase * HH;
        float* redS = (float*)(sm + SM_RED);
        float* redQ = redS + 256;
        float* redA = redQ + 256;

#pragma unroll
        for (int nt = 0; nt < 4; nt++) {
            int lc = wn * 32 + nt * 8 + t2;     // local col 0..63
            int c  = n0 + lc;                   // global col
            float c2a = c2s[lc], c2b = c2s[lc + 1];
            float pS0 = 0.f, pS1 = 0.f, pQ0 = 0.f, pQ1 = 0.f, pA0 = 0.f, pA1 = 0.f;
#pragma unroll
            for (int mt = 0; mt < 2; mt++) {
#pragma unroll
                for (int h = 0; h < 2; h++) {
                    int r = wm * 32 + mt * 16 + h * 8 + g;
                    float2 ahv = *(const float2*)&ahB[(size_t)r * HH + c];
                    float2 vhv = *(const float2*)&vhB[(size_t)r * HH + c];
                    __half2 lo = *reinterpret_cast<__half2*>(&dl[mt][nt][h]);
                    float x0 = fmaf(__low2float(lo),  LO_UNSCALE, d[mt][nt][h * 2 + 0]) + c2a + ahv.x;
                    float x1 = fmaf(__high2float(lo), LO_UNSCALE, d[mt][nt][h * 2 + 1]) + c2b + ahv.y;
                    *(float2*)&enB[(size_t)r * HH + c] = make_float2(x0, x1);
                    pS0 += x0; pS1 += x1;
                    pQ0 = fmaf(x0, x0, pQ0); pQ1 = fmaf(x1, x1, pQ1);
                    pA0 = fmaf(vhv.x, 1.f / (1.f + __expf(-x0)), pA0);
                    pA1 = fmaf(vhv.y, 1.f / (1.f + __expf(-x1)), pA1);
                }
            }
#pragma unroll
            for (int m = 4; m <= 16; m <<= 1) {
                pS0 += __shfl_xor_sync(0xffffffffu, pS0, m);
                pS1 += __shfl_xor_sync(0xffffffffu, pS1, m);
                pQ0 += __shfl_xor_sync(0xffffffffu, pQ0, m);
                pQ1 += __shfl_xor_sync(0xffffffffu, pQ1, m);
                pA0 += __shfl_xor_sync(0xffffffffu, pA0, m);
                pA1 += __shfl_xor_sync(0xffffffffu, pA1, m);
            }
            if (g == 0) {
                redS[wm * 64 + lc] = pS0; redS[wm * 64 + lc + 1] = pS1;
                redQ[wm * 64 + lc] = pQ0; redQ[wm * 64 + lc + 1] = pQ1;
                redA[wm * 64 + lc] = pA0; redA[wm * 64 + lc + 1] = pA1;
            }
        }
    }
    __syncthreads();
    if (tid < 64) {
        float* redS = (float*)(sm + SM_RED);
        float* redQ = redS + 256;
        float* redA = redQ + 256;
        float S = 0.f, Q = 0.f, A = 0.f;
#pragma unroll
        for (int w = 0; w < 4; w++) {
            S += redS[w * 64 + tid];
            Q += redQ[w * 64 + tid];
            A += redA[w * 64 + tid];
        }
        int n = n0 + tid;
        g_statS[(size_t)n * NBLK2 + rowblk] = S;
        g_statQ[(size_t)n * NBLK2 + rowblk] = Q;
        g_aggp[(size_t)n * NBLK2 + rowblk]  = A;
    }
}

// ---------------- K0: four small linears + Cw pre-convert (y==4) ----------------
constexpr int WS_STRIDE = 132;
constexpr int SMEM_LIN = (HH * WS_STRIDE + 64 * HH) * 4;

__device__ __forceinline__ void fma2(unsigned long long& d, unsigned long long a, unsigned long long b) {
    asm("fma.rn.f32x2 %0, %1, %2, %0;" : "+l"(d) : "l"(a), "l"(b));
}
__device__ __forceinline__ float2 unpack2(unsigned long long v) {
    float2 r; asm("mov.b64 {%0,%1}, %2;" : "=f"(r.x), "=f"(r.y) : "l"(v)); return r;
}

__global__ void k_lin(const float* __restrict__ h,
                      const float* __restrict__ W0, const float* __restrict__ b0,
                      const float* __restrict__ W1, const float* __restrict__ b1,
                      const float* __restrict__ W2, const float* __restrict__ b2,
                      const float* __restrict__ W3, const float* __restrict__ b3,
                      const float* __restrict__ Cw) {
    if (blockIdx.y == 4) {
        // 4 B tiles: [nh][ch], each 64 N-rows x 64 K fp16, LDC stride
        if (blockIdx.x >= 4) return;
        int nh = blockIdx.x >> 1, ch = blockIdx.x & 1;
        char* dst = g_bt + (size_t)(nh * 2 + ch) * B_TILE;
        const float* wb = Cw + (size_t)(nh * 64) * HH + ch * 64;
        for (int idx = threadIdx.x; idx < 64 * 16; idx += 256) {
            int row = idx >> 4, c4 = idx & 15;
            uint32_t off = (uint32_t)row * (LDC * 2) + c4 * 8;
            float4 wv = *(const float4*)&wb[(size_t)row * HH + c4 * 4];
            cvtB_store4(wv, dst, off);
        }
        return;
    }
    extern __shared__ float smf[];
    float* Ws = smf;
    float* As = Ws + HH * WS_STRIDE;

    int m = blockIdx.y;
    const float* W    = (m == 0) ? W0 : (m == 1) ? W1 : (m == 2) ? W2 : W3;
    const float* bias = (m == 0) ? b0 : (m == 1) ? b1 : (m == 2) ? b2 : b3;

    int tid = threadIdx.x;
    for (int i = tid; i < HH * 32; i += 256) {
        int n = i >> 5, kc = i & 31;
        *(float4*)&Ws[n * WS_STRIDE + kc * 4] = *(const float4*)&W[n * HH + kc * 4];
    }
    int r0 = blockIdx.x * 64;
    const float4* hsrc = (const float4*)(h + (size_t)r0 * HH);
    for (int i = tid; i < 64 * 32; i += 256) ((float4*)As)[i] = hsrc[i];
    __syncthreads();

    int tr = tid >> 5, tc = tid & 31;
    int jj0 = tr * 8;
    unsigned long long acc[8][4];
#pragma unroll
    for (int jl = 0; jl < 8; jl++)
#pragma unroll
        for (int mm = 0; mm < 4; mm++) acc[jl][mm] = 0ull;
#pragma unroll 4
    for (int k = 0; k < HH; k += 4) {
        ulonglong2 w0 = *(const ulonglong2*)&Ws[(tc +  0) * WS_STRIDE + k];
        ulonglong2 w1 = *(const ulonglong2*)&Ws[(tc + 32) * WS_STRIDE + k];
        ulonglong2 w2 = *(const ulonglong2*)&Ws[(tc + 64) * WS_STRIDE + k];
        ulonglong2 w3 = *(const ulonglong2*)&Ws[(tc + 96) * WS_STRIDE + k];
#pragma unroll
        for (int jl = 0; jl < 8; jl++) {
            ulonglong2 a = *(const ulonglong2*)&As[(jj0 + jl) * HH + k];
            fma2(acc[jl][0], a.x, w0.x); fma2(acc[jl][0], a.y, w0.y);
            fma2(acc[jl][1], a.x, w1.x); fma2(acc[jl][1], a.y, w1.y);
            fma2(acc[jl][2], a.x, w2.x); fma2(acc[jl][2], a.y, w2.y);
            fma2(acc[jl][3], a.x, w3.x); fma2(acc[jl][3], a.y, w3.y);
        }
    }
    float bv[4];
#pragma unroll
    for (int mm = 0; mm < 4; mm++) bv[mm] = bias[tc + 32 * mm];
    float* dst = g_lin + (size_t)m * ROWS_H * HH;
#pragma unroll
    for (int jl = 0; jl < 8; jl++) {
        size_t row = (size_t)(r0 + jj0 + jl) * HH;
#pragma unroll
        for (int mm = 0; mm < 4; mm++) {
            float2 p = unpack2(acc[jl][mm]);
            dst[row + tc + 32 * mm] = p.x + p.y + bv[mm];
        }
    }
}

// ---------------- K2: stats reduce (fp64) + h path + h_out ----------------
__device__ __forceinline__ double blk_red(double v, double* sb) {
    int tid = threadIdx.x;
    sb[tid] = v; __syncthreads();
    for (int o = 128; o > 0; o >>= 1) {
        if (tid < o) sb[tid] += sb[tid + o];
        __syncthreads();
    }
    double r = sb[0]; __syncthreads();
    return r;
}

__global__ void k_finalize(const float* __restrict__ h_in,
                           const float* __restrict__ gamma_h, const float* __restrict__ beta_h,
                           const float* __restrict__ gamma_e, const float* __restrict__ beta_e,
                           float* __restrict__ out_h) {
    __shared__ double sb[256];
    __shared__ float sbroad[2];
    int n = blockIdx.x;
    int tid = threadIdx.x;

    double s = 0.0, q = 0.0;
    for (int p = tid; p < NBLK2; p += 256) {
        s += (double)g_statS[(size_t)n * NBLK2 + p];
        q += (double)g_statQ[(size_t)n * NBLK2 + p];
    }
    s = blk_red(s, sb);
    q = blk_red(q, sb);
    if (tid == 0) {
        double mean = s / (double)ROWS_E;
        double var  = q / (double)ROWS_E - mean * mean;
        float rstd  = (float)(1.0 / sqrt(var + (double)EPS));
        float sc    = gamma_e[n] * rstd;
        g_scaleE[n] = sc;
        g_shiftE[n] = beta_e[n] - (float)mean * sc;
    }

    double hs = 0.0, hq = 0.0;
    for (int r = tid; r < ROWS_H; r += 256) {
        const float* ap = &g_aggp[(size_t)n * NBLK2 + r * 2];
        float agg = ap[0] + ap[1];
        float hn  = g_lin[(size_t)r * HH + n] + agg;  // Uh + agg
        g_hnew[(size_t)r * HH + n] = hn;
        hs += (double)hn; hq += (double)hn * (double)hn;
    }
    hs = blk_red(hs, sb);
    hq = blk_red(hq, sb);
    if (tid == 0) {
        double mean = hs / (double)ROWS_H;
        double var  = hq / (double)ROWS_H - mean * mean;
        float rstd  = (float)(1.0 / sqrt(var + (double)EPS));
        float sc    = gamma_h[n] * rstd;
        sbroad[0]   = sc;
        sbroad[1]   = beta_h[n] - (float)mean * sc;
    }
    __syncthreads();
    float sc = sbroad[0], sh = sbroad[1];
    for (int r = tid; r < ROWS_H; r += 256) {
        float v = fmaf(g_hnew[(size_t)r * HH + n], sc, sh);
        out_h[(size_t)r * HH + n] = h_in[(size_t)r * HH + n] + fmaxf(v, 0.f);
    }
}

// ---------------- K3: e epilogue ----------------
__global__ void k_epi(const float* __restrict__ e_in, float* __restrict__ out_e) {
    int tid = threadIdx.x;
    const float4* en4 = (const float4*)g_enew;
    const float4* ei4 = (const float4*)e_in;
    const float4* sc4 = (const float4*)g_scaleE;
    const float4* sh4 = (const float4*)g_shiftE;
    float4* out4 = (float4*)out_e;
#pragma unroll
    for (int it = 0; it < 4; it++) {
        size_t f = (size_t)blockIdx.x * 1024 + it * 256 + tid;
        int c = (int)(f & 31);
        float4 sc = __ldg(&sc4[c]);
        float4 sh = __ldg(&sh4[c]);
        float4 x  = en4[f];
        float4 ei = ei4[f];
        float4 o;
        o.x = ei.x + fmaxf(fmaf(x.x, sc.x, sh.x), 0.f);
        o.y = ei.y + fmaxf(fmaf(x.y, sc.y, sh.y), 0.f);
        o.z = ei.z + fmaxf(fmaf(x.z, sc.z, sh.z), 0.f);
        o.w = ei.w + fmaxf(fmaf(x.w, sc.w, sh.w), 0.f);
        out4[f] = o;
    }
}

extern "C" void kernel_launch(void* const* d_in, const int* in_sizes, int n_in,
                              void* d_out, int out_size) {
    (void)in_sizes; (void)n_in; (void)out_size;
    const float* h  = (const float*)d_in[0];
    const float* e  = (const float*)d_in[1];
    const float* Uw = (const float*)d_in[3];
    const float* Ub = (const float*)d_in[4];
    const float* Vw = (const float*)d_in[5];
    const float* Vb = (const float*)d_in[6];
    const float* Aw = (const float*)d_in[7];
    const float* Ab = (const float*)d_in[8];
    const float* Bw = (const float*)d_in[9];
    const float* Bb = (const float*)d_in[10];
    const float* Cw = (const float*)d_in[11];
    const float* Cb = (const float*)d_in[12];
    const float* gh = (const float*)d_in[13];
    const float* bh = (const float*)d_in[14];
    const float* ge = (const float*)d_in[15];
    const float* be = (const float*)d_in[16];
    float* out = (float*)d_out;   // [h_out (131072) | e_out (33554432)]

    cudaFuncSetAttribute(k_lin,  cudaFuncAttributeMaxDynamicSharedMemorySize, SMEM_LIN);
    cudaFuncSetAttribute(k_main, cudaFuncAttributeMaxDynamicSharedMemorySize, SM_TOTAL);

    k_lin<<<dim3(ROWS_H / 64, 5), 256, SMEM_LIN>>>(h, Uw, Ub, Vw, Vb, Aw, Ab, Bw, Bb, Cw);
    k_main<<<GRID_MAIN, 256, SM_TOTAL>>>(e, Cb);
    k_finalize<<<HH, 256>>>(h, gh, bh, ge, be, out);
    k_epi<<<ROWS_E * HH / 4096, 256>>>(e, out + ROWS_H * HH);
}

// round 14
// speedup vs baseline: 1.2318x; 1.2318x over previous
#include <cuda_runtime.h>
#include <cuda_fp16.h>
#include <cstdint>

// Problem constants
#define BB 4
#define VV 256
#define HH 128
constexpr int ROWS_H = BB * VV;           // 1024
constexpr int ROWS_E = BB * VV * VV;      // 262144
constexpr int TM     = 128;               // e-rows per block in k_main
constexpr int NBLK2  = ROWS_E / TM;       // 2048
constexpr float EPS  = 1e-5f;

// ---------------- smem geometry for k_main (fp16 single-pass, K chunked 2x64) ----------------
constexpr int LDC    = 72;                  // fp16 elems per tile row (144 B; 9 units, odd)
constexpr int TILE_B = 128 * LDC * 2;       // 18432 B per fp16 tile (128 rows x 64 cols)
constexpr int LDSG   = 68;                  // f32 stage row stride
constexpr int SM_C2  = 0;                   // 128 floats
constexpr int SM_AHI = 1024;
constexpr int SM_BW0 = SM_AHI + TILE_B;     // 19456
constexpr int SM_BW1 = SM_BW0 + TILE_B;     // 37888
constexpr int SM_STG = SM_BW1 + TILE_B;     // 56320 (128 x 68 f32 = 34816)
constexpr int SM_RED = SM_STG + 128 * LDSG * 4;  // 91136 (3 x 512 floats)
constexpr int SM_TOTAL = SM_RED + 6144;     // 97280 -> 2 CTAs/SM

// Scratch
__device__ float g_enew[(size_t)ROWS_E * HH];   // 134 MB
__device__ float g_lin[4 * ROWS_H * HH];        // Uh,Vh,Ah,Bh
__device__ __align__(16) char g_bt[2 * TILE_B]; // pre-converted Cw fp16 [chunk]
__device__ float g_statS[HH * NBLK2];
__device__ float g_statQ[HH * NBLK2];
__device__ float g_aggp[HH * NBLK2];
__device__ float g_hnew[ROWS_H * HH];
__device__ float g_scaleE[HH];
__device__ float g_shiftE[HH];

__device__ __forceinline__ uint32_t smem_u32(const void* p) {
    uint32_t a;
    asm("{ .reg .u64 t; cvta.to.shared.u64 t, %1; cvt.u32.u64 %0, t; }" : "=r"(a) : "l"(p));
    return a;
}
__device__ __forceinline__ void ldmatrix_x4(uint32_t& r0, uint32_t& r1, uint32_t& r2, uint32_t& r3, uint32_t addr) {
    asm volatile("ldmatrix.sync.aligned.m8n8.x4.shared.b16 {%0,%1,%2,%3}, [%4];"
        : "=r"(r0), "=r"(r1), "=r"(r2), "=r"(r3) : "r"(addr) : "memory");
}
__device__ __forceinline__ void mma16816(float (&d)[4], const uint32_t (&a)[4], uint32_t b0, uint32_t b1) {
    asm("mma.sync.aligned.m16n8k16.row.col.f32.f16.f16.f32 "
        "{%0,%1,%2,%3}, {%4,%5,%6,%7}, {%8,%9}, {%0,%1,%2,%3};"
        : "+f"(d[0]), "+f"(d[1]), "+f"(d[2]), "+f"(d[3])
        : "r"(a[0]), "r"(a[1]), "r"(a[2]), "r"(a[3]), "r"(b0), "r"(b1));
}
__device__ __forceinline__ void cp_async16(uint32_t smem_dst, const void* gmem_src) {
    asm volatile("cp.async.cg.shared.global [%0], [%1], 16;" :: "r"(smem_dst), "l"(gmem_src) : "memory");
}
#define CP_COMMIT() asm volatile("cp.async.commit_group;" ::: "memory")
#define CP_WAIT(n)  asm volatile("cp.async.wait_group %0;" :: "n"(n) : "memory")

// single-pass fp16 conversion (one tile)
__device__ __forceinline__ void cvt_store4(float4 v, char* smem, uint32_t off) {
    __half h0 = __float2half_rn(v.x), h1 = __float2half_rn(v.y);
    __half h2 = __float2half_rn(v.z), h3 = __float2half_rn(v.w);
    uint2 u;
    u.x = ((uint32_t)__half_as_ushort(h1) << 16) | __half_as_ushort(h0);
    u.y = ((uint32_t)__half_as_ushort(h3) << 16) | __half_as_ushort(h2);
    *(uint2*)(smem + off) = u;
}

// ---------------- K1: HMMA Ce GEMM (fp16 single-pass) + e_new + gates + agg + stats ----------------
__global__ void __launch_bounds__(256, 2)
k_main(const float* __restrict__ e, const float* __restrict__ Cb) {
    extern __shared__ char sm[];
    uint32_t smb = smem_u32(sm);
    int tid = threadIdx.x;
    int wid = tid >> 5, lane = tid & 31;

    int blk = blockIdx.x;
    int rbase = blk * TM;
    int bi = blk >> 1;            // b*V + i
    int b  = bi >> 8;
    int j0 = (blk & 1) * TM;      // j range start

    // c2 = Cb + Bh[bi]
    if (tid < HH)
        ((float*)(sm + SM_C2))[tid] = Cb[tid] + g_lin[(size_t)3 * ROWS_H * HH + (size_t)bi * HH + tid];

    // group 1: both B chunk tiles
    for (int i = tid; i < 2 * TILE_B / 16; i += 256)
        cp_async16(smb + SM_BW0 + i * 16, g_bt + i * 16);
    CP_COMMIT();
    // group 2: stage chunk-1 A (f32)
    {
        const float* eb1 = e + (size_t)rbase * HH + 64;
        for (int i = tid; i < 128 * 16; i += 256) {
            int row = i >> 4, seg = i & 15;
            cp_async16(smb + SM_STG + (uint32_t)(row * LDSG + seg * 4) * 4,
                       eb1 + (size_t)row * HH + seg * 4);
        }
    }
    CP_COMMIT();

    // chunk-0 A: direct load + convert
    {
        const float* eb = e + (size_t)rbase * HH;
        for (int idx = tid; idx < 128 * 16; idx += 256) {
            int row = idx >> 4, c4 = idx & 15;
            uint32_t off = (uint32_t)row * (LDC * 2) + c4 * 8;
            float4 ev = *(const float4*)&eb[(size_t)row * HH + c4 * 4];
            cvt_store4(ev, sm, SM_AHI + off);
        }
    }

    int wm = wid >> 1, wn = wid & 1;     // 4 x 2 warp grid, warp tile 32x64
    float d[2][8][4];
#pragma unroll
    for (int mt = 0; mt < 2; mt++)
#pragma unroll
        for (int nt = 0; nt < 8; nt++)
#pragma unroll
            for (int q = 0; q < 4; q++) d[mt][nt][q] = 0.f;

    uint32_t aLaneOff = (uint32_t)(wm * 32 + (lane & 15)) * (LDC * 2) + (lane >> 4) * 16;
    uint32_t bLaneOff = (uint32_t)(wn * 64 + (((lane >> 4) & 1) * 8) + (lane & 7)) * (LDC * 2)
                      + ((lane >> 3) & 1) * 16;

#pragma unroll
    for (int ch = 0; ch < 2; ch++) {
        if (ch == 0) { CP_WAIT(1); }     // B tiles ready; A stage may still fly
        __syncthreads();

        uint32_t aBase = smb + SM_AHI + aLaneOff;
        uint32_t bBase = smb + (ch ? SM_BW1 : SM_BW0) + bLaneOff;
#pragma unroll
        for (int kk = 0; kk < 4; kk++) {
            uint32_t bb[16];
#pragma unroll
            for (int q = 0; q < 4; q++)
                ldmatrix_x4(bb[q * 4], bb[q * 4 + 1], bb[q * 4 + 2], bb[q * 4 + 3],
                            bBase + kk * 32 + (uint32_t)q * 16 * (LDC * 2));
            uint32_t a0[4], a1[4];
            ldmatrix_x4(a0[0], a0[1], a0[2], a0[3], aBase + kk * 32);
            ldmatrix_x4(a1[0], a1[1], a1[2], a1[3], aBase + kk * 32 + 16 * (LDC * 2));
#pragma unroll
            for (int nt = 0; nt < 8; nt++) {
                uint32_t b0 = bb[(nt >> 1) * 4 + (nt & 1) * 2];
                uint32_t b1 = bb[(nt >> 1) * 4 + (nt & 1) * 2 + 1];
                mma16816(d[0][nt], a0, b0, b1);
                mma16816(d[1][nt], a1, b0, b1);
            }
        }
        __syncthreads();   // A tile consumed
        if (ch == 0) {
            CP_WAIT(0);    // staged chunk-1 ready
            const float* stg = (const float*)(sm + SM_STG);
            for (int idx = tid; idx < 128 * 16; idx += 256) {
                int row = idx >> 4, c4 = idx & 15;
                uint32_t off = (uint32_t)row * (LDC * 2) + c4 * 8;
                float4 ev = *(const float4*)&stg[row * LDSG + c4 * 4];
                cvt_store4(ev, sm, SM_AHI + off);
            }
        }
    }

    // -------- fragment-direct epilogue --------
    {
        int g = lane >> 2, t2 = (lane & 3) * 2;
        const float* c2s = (const float*)(sm + SM_C2);
        const float* ahB = g_lin + (size_t)2 * ROWS_H * HH + (size_t)(b * VV + j0) * HH;
        const float* vhB = g_lin + (size_t)1 * ROWS_H * HH + (size_t)(b * VV + j0) * HH;
        float* enB = g_enew + (size_t)rbase * HH;
        float* redS = (float*)(sm + SM_RED);
        float* redQ = redS + 512;
        float* redA = redQ + 512;

#pragma unroll
        for (int nt = 0; nt < 8; nt++) {
            int c = wn * 64 + nt * 8 + t2;
            float c2a = c2s[c], c2b = c2s[c + 1];
            float pS0 = 0.f, pS1 = 0.f, pQ0 = 0.f, pQ1 = 0.f, pA0 = 0.f, pA1 = 0.f;
#pragma unroll
            for (int mt = 0; mt < 2; mt++) {
#pragma unroll
                for (int h = 0; h < 2; h++) {
                    int r = wm * 32 + mt * 16 + h * 8 + g;
                    float2 ahv = *(const float2*)&ahB[(size_t)r * HH + c];
                    float2 vhv = *(const float2*)&vhB[(size_t)r * HH + c];
                    float x0 = d[mt][nt][h * 2 + 0] + c2a + ahv.x;
                    float x1 = d[mt][nt][h * 2 + 1] + c2b + ahv.y;
                    *(float2*)&enB[(size_t)r * HH + c] = make_float2(x0, x1);
                    pS0 += x0; pS1 += x1;
                    pQ0 = fmaf(x0, x0, pQ0); pQ1 = fmaf(x1, x1, pQ1);
                    pA0 = fmaf(vhv.x, 1.f / (1.f + __expf(-x0)), pA0);
                    pA1 = fmaf(vhv.y, 1.f / (1.f + __expf(-x1)), pA1);
                }
            }
#pragma unroll
            for (int m = 4; m <= 16; m <<= 1) {
                pS0 += __shfl_xor_sync(0xffffffffu, pS0, m);
                pS1 += __shfl_xor_sync(0xffffffffu, pS1, m);
                pQ0 += __shfl_xor_sync(0xffffffffu, pQ0, m);
                pQ1 += __shfl_xor_sync(0xffffffffu, pQ1, m);
                pA0 += __shfl_xor_sync(0xffffffffu, pA0, m);
                pA1 += __shfl_xor_sync(0xffffffffu, pA1, m);
            }
            if (g == 0) {
                redS[wm * 128 + c] = pS0; redS[wm * 128 + c + 1] = pS1;
                redQ[wm * 128 + c] = pQ0; redQ[wm * 128 + c + 1] = pQ1;
                redA[wm * 128 + c] = pA0; redA[wm * 128 + c + 1] = pA1;
            }
        }
    }
    __syncthreads();
    if (tid < HH) {
        float* redS = (float*)(sm + SM_RED);
        float* redQ = redS + 512;
        float* redA = redQ + 512;
        float S = 0.f, Q = 0.f, A = 0.f;
#pragma unroll
        for (int w = 0; w < 4; w++) {
            S += redS[w * 128 + tid];
            Q += redQ[w * 128 + tid];
            A += redA[w * 128 + tid];
        }
        g_statS[(size_t)tid * NBLK2 + blk] = S;
        g_statQ[(size_t)tid * NBLK2 + blk] = Q;
        g_aggp[(size_t)tid * NBLK2 + blk]  = A;
    }
}

// ---------------- K0: four small linears + Cw pre-convert (y==4) ----------------
constexpr int WS_STRIDE = 132;
constexpr int SMEM_LIN = (HH * WS_STRIDE + 64 * HH) * 4;

__device__ __forceinline__ void fma2(unsigned long long& d, unsigned long long a, unsigned long long b) {
    asm("fma.rn.f32x2 %0, %1, %2, %0;" : "+l"(d) : "l"(a), "l"(b));
}
__device__ __forceinline__ float2 unpack2(unsigned long long v) {
    float2 r; asm("mov.b64 {%0,%1}, %2;" : "=f"(r.x), "=f"(r.y) : "l"(v)); return r;
}

__global__ void k_lin(const float* __restrict__ h,
                      const float* __restrict__ W0, const float* __restrict__ b0,
                      const float* __restrict__ W1, const float* __restrict__ b1,
                      const float* __restrict__ W2, const float* __restrict__ b2,
                      const float* __restrict__ W3, const float* __restrict__ b3,
                      const float* __restrict__ Cw) {
    if (blockIdx.y == 4) {
        int ch = blockIdx.x & 1;
        if (blockIdx.x >= 2) return;
        char* dst = g_bt + (size_t)ch * TILE_B;
        const float* wb = Cw + ch * 64;
        for (int idx = threadIdx.x; idx < 128 * 16; idx += 256) {
            int row = idx >> 4, c4 = idx & 15;
            uint32_t off = (uint32_t)row * (LDC * 2) + c4 * 8;
            float4 wv = *(const float4*)&wb[(size_t)row * HH + c4 * 4];
            cvt_store4(wv, dst, off);
        }
        return;
    }
    extern __shared__ float smf[];
    float* Ws = smf;
    float* As = Ws + HH * WS_STRIDE;

    int m = blockIdx.y;
    const float* W    = (m == 0) ? W0 : (m == 1) ? W1 : (m == 2) ? W2 : W3;
    const float* bias = (m == 0) ? b0 : (m == 1) ? b1 : (m == 2) ? b2 : b3;

    int tid = threadIdx.x;
    for (int i = tid; i < HH * 32; i += 256) {
        int n = i >> 5, kc = i & 31;
        *(float4*)&Ws[n * WS_STRIDE + kc * 4] = *(const float4*)&W[n * HH + kc * 4];
    }
    int r0 = blockIdx.x * 64;
    const float4* hsrc = (const float4*)(h + (size_t)r0 * HH);
    for (int i = tid; i < 64 * 32; i += 256) ((float4*)As)[i] = hsrc[i];
    __syncthreads();

    int tr = tid >> 5, tc = tid & 31;
    int jj0 = tr * 8;
    unsigned long long acc[8][4];
#pragma unroll
    for (int jl = 0; jl < 8; jl++)
#pragma unroll
        for (int mm = 0; mm < 4; mm++) acc[jl][mm] = 0ull;
#pragma unroll 4
    for (int k = 0; k < HH; k += 4) {
        ulonglong2 w0 = *(const ulonglong2*)&Ws[(tc +  0) * WS_STRIDE + k];
        ulonglong2 w1 = *(const ulonglong2*)&Ws[(tc + 32) * WS_STRIDE + k];
        ulonglong2 w2 = *(const ulonglong2*)&Ws[(tc + 64) * WS_STRIDE + k];
        ulonglong2 w3 = *(const ulonglong2*)&Ws[(tc + 96) * WS_STRIDE + k];
#pragma unroll
        for (int jl = 0; jl < 8; jl++) {
            ulonglong2 a = *(const ulonglong2*)&As[(jj0 + jl) * HH + k];
            fma2(acc[jl][0], a.x, w0.x); fma2(acc[jl][0], a.y, w0.y);
            fma2(acc[jl][1], a.x, w1.x); fma2(acc[jl][1], a.y, w1.y);
            fma2(acc[jl][2], a.x, w2.x); fma2(acc[jl][2], a.y, w2.y);
            fma2(acc[jl][3], a.x, w3.x); fma2(acc[jl][3], a.y, w3.y);
        }
    }
    float bv[4];
#pragma unroll
    for (int mm = 0; mm < 4; mm++) bv[mm] = bias[tc + 32 * mm];
    float* dst = g_lin + (size_t)m * ROWS_H * HH;
#pragma unroll
    for (int jl = 0; jl < 8; jl++) {
        size_t row = (size_t)(r0 + jj0 + jl) * HH;
#pragma unroll
        for (int mm = 0; mm < 4; mm++) {
            float2 p = unpack2(acc[jl][mm]);
            dst[row + tc + 32 * mm] = p.x + p.y + bv[mm];
        }
    }
}

// ---------------- K2: stats reduce (fp64) + h path + h_out ----------------
__device__ __forceinline__ double blk_red(double v, double* sb) {
    int tid = threadIdx.x;
    sb[tid] = v; __syncthreads();
    for (int o = 128; o > 0; o >>= 1) {
        if (tid < o) sb[tid] += sb[tid + o];
        __syncthreads();
    }
    double r = sb[0]; __syncthreads();
    return r;
}

__global__ void k_finalize(const float* __restrict__ h_in,
                           const float* __restrict__ gamma_h, const float* __restrict__ beta_h,
                           const float* __restrict__ gamma_e, const float* __restrict__ beta_e,
                           float* __restrict__ out_h) {
    __shared__ double sb[256];
    __shared__ float sbroad[2];
    int n = blockIdx.x;
    int tid = threadIdx.x;

    double s = 0.0, q = 0.0;
    for (int p = tid; p < NBLK2; p += 256) {
        s += (double)g_statS[(size_t)n * NBLK2 + p];
        q += (double)g_statQ[(size_t)n * NBLK2 + p];
    }
    s = blk_red(s, sb);
    q = blk_red(q, sb);
    if (tid == 0) {
        double mean = s / (double)ROWS_E;
        double var  = q / (double)ROWS_E - mean * mean;
        float rstd  = (float)(1.0 / sqrt(var + (double)EPS));
        float sc    = gamma_e[n] * rstd;
        g_scaleE[n] = sc;
        g_shiftE[n] = beta_e[n] - (float)mean * sc;
    }

    double hs = 0.0, hq = 0.0;
    for (int r = tid; r < ROWS_H; r += 256) {
        const float* ap = &g_aggp[(size_t)n * NBLK2 + r * 2];
        float agg = ap[0] + ap[1];
        float hn  = g_lin[(size_t)r * HH + n] + agg;  // Uh + agg
        g_hnew[(size_t)r * HH + n] = hn;
        hs += (double)hn; hq += (double)hn * (double)hn;
    }
    hs = blk_red(hs, sb);
    hq = blk_red(hq, sb);
    if (tid == 0) {
        double mean = hs / (double)ROWS_H;
        double var  = hq / (double)ROWS_H - mean * mean;
        float rstd  = (float)(1.0 / sqrt(var + (double)EPS));
        float sc    = gamma_h[n] * rstd;
        sbroad[0]   = sc;
        sbroad[1]   = beta_h[n] - (float)mean * sc;
    }
    __syncthreads();
    float sc = sbroad[0], sh = sbroad[1];
    for (int r = tid; r < ROWS_H; r += 256) {
        float v = fmaf(g_hnew[(size_t)r * HH + n], sc, sh);
        out_h[(size_t)r * HH + n] = h_in[(size_t)r * HH + n] + fmaxf(v, 0.f);
    }
}

// ---------------- K3: e epilogue ----------------
__global__ void k_epi(const float* __restrict__ e_in, float* __restrict__ out_e) {
    int tid = threadIdx.x;
    const float4* en4 = (const float4*)g_enew;
    const float4* ei4 = (const float4*)e_in;
    const float4* sc4 = (const float4*)g_scaleE;
    const float4* sh4 = (const float4*)g_shiftE;
    float4* out4 = (float4*)out_e;
#pragma unroll
    for (int it = 0; it < 4; it++) {
        size_t f = (size_t)blockIdx.x * 1024 + it * 256 + tid;
        int c = (int)(f & 31);
        float4 sc = __ldg(&sc4[c]);
        float4 sh = __ldg(&sh4[c]);
        float4 x  = en4[f];
        float4 ei = ei4[f];
        float4 o;
        o.x = ei.x + fmaxf(fmaf(x.x, sc.x, sh.x), 0.f);
        o.y = ei.y + fmaxf(fmaf(x.y, sc.y, sh.y), 0.f);
        o.z = ei.z + fmaxf(fmaf(x.z, sc.z, sh.z), 0.f);
        o.w = ei.w + fmaxf(fmaf(x.w, sc.w, sh.w), 0.f);
        out4[f] = o;
    }
}

extern "C" void kernel_launch(void* const* d_in, const int* in_sizes, int n_in,
                              void* d_out, int out_size) {
    (void)in_sizes; (void)n_in; (void)out_size;
    const float* h  = (const float*)d_in[0];
    const float* e  = (const float*)d_in[1];
    const float* Uw = (const float*)d_in[3];
    const float* Ub = (const float*)d_in[4];
    const float* Vw = (const float*)d_in[5];
    const float* Vb = (const float*)d_in[6];
    const float* Aw = (const float*)d_in[7];
    const float* Ab = (const float*)d_in[8];
    const float* Bw = (const float*)d_in[9];
    const float* Bb = (const float*)d_in[10];
    const float* Cw = (const float*)d_in[11];
    const float* Cb = (const float*)d_in[12];
    const float* gh = (const float*)d_in[13];
    const float* bh = (const float*)d_in[14];
    const float* ge = (const float*)d_in[15];
    const float* be = (const float*)d_in[16];
    float* out = (float*)d_out;   // [h_out (131072) | e_out (33554432)]

    cudaFuncSetAttribute(k_lin,  cudaFuncAttributeMaxDynamicSharedMemorySize, SMEM_LIN);
    cudaFuncSetAttribute(k_main, cudaFuncAttributeMaxDynamicSharedMemorySize, SM_TOTAL);

    k_lin<<<dim3(ROWS_H / 64, 5), 256, SMEM_LIN>>>(h, Uw, Ub, Vw, Vb, Aw, Ab, Bw, Bb, Cw);
    k_main<<<NBLK2, 256, SM_TOTAL>>>(e, Cb);
    k_finalize<<<HH, 256>>>(h, gh, bh, ge, be, out);
    k_epi<<<ROWS_E * HH / 4096, 256>>>(e, out + ROWS_H * HH);
}

// round 15
// speedup vs baseline: 1.2339x; 1.0017x over previous
#include <cuda_runtime.h>
#include <cuda_fp16.h>
#include <cstdint>

// Problem constants
#define BB 4
#define VV 256
#define HH 128
constexpr int ROWS_H = BB * VV;           // 1024
constexpr int ROWS_E = BB * VV * VV;      // 262144
constexpr int NBLK2  = ROWS_E / 128;      // 2048 stat row-blocks (128 rows each)
constexpr int GRID_MAIN = ROWS_E / 256;   // 1024 (one block per (b,i))
constexpr float EPS  = 1e-5f;

// ---------------- smem geometry for k_main ----------------
constexpr int LDC    = 72;                  // fp16 elems per tile row (144 B; 9 units, odd)
constexpr int TILE_B = 128 * LDC * 2;       // 18432 B per fp16 tile (128 rows x 64 cols)
constexpr int SM_C2  = 0;                   // 128 floats
constexpr int SM_AHI = 1024;
constexpr int SM_BW0 = SM_AHI + TILE_B;     // 19456
constexpr int SM_BW1 = SM_BW0 + TILE_B;     // 37888
constexpr int SM_RED = SM_BW1 + TILE_B;     // 56320 (3 x 512 floats)
constexpr int SM_TOTAL = SM_RED + 6144;     // 62464 -> 2 CTAs/SM easily

// Scratch
__device__ float g_enew[(size_t)ROWS_E * HH];   // 134 MB
__device__ float g_lin[4 * ROWS_H * HH];        // Uh,Vh,Ah,Bh
__device__ __align__(16) char g_bt[2 * TILE_B]; // pre-converted Cw fp16 [chunk]
__device__ float g_statS[HH * NBLK2];
__device__ float g_statQ[HH * NBLK2];
__device__ float g_aggp[HH * NBLK2];
__device__ float g_hnew[ROWS_H * HH];
__device__ float g_scaleE[HH];
__device__ float g_shiftE[HH];

__device__ __forceinline__ uint32_t smem_u32(const void* p) {
    uint32_t a;
    asm("{ .reg .u64 t; cvta.to.shared.u64 t, %1; cvt.u32.u64 %0, t; }" : "=r"(a) : "l"(p));
    return a;
}
__device__ __forceinline__ void ldmatrix_x4(uint32_t& r0, uint32_t& r1, uint32_t& r2, uint32_t& r3, uint32_t addr) {
    asm volatile("ldmatrix.sync.aligned.m8n8.x4.shared.b16 {%0,%1,%2,%3}, [%4];"
        : "=r"(r0), "=r"(r1), "=r"(r2), "=r"(r3) : "r"(addr) : "memory");
}
__device__ __forceinline__ void mma16816(float (&d)[4], const uint32_t (&a)[4], uint32_t b0, uint32_t b1) {
    asm("mma.sync.aligned.m16n8k16.row.col.f32.f16.f16.f32 "
        "{%0,%1,%2,%3}, {%4,%5,%6,%7}, {%8,%9}, {%0,%1,%2,%3};"
        : "+f"(d[0]), "+f"(d[1]), "+f"(d[2]), "+f"(d[3])
        : "r"(a[0]), "r"(a[1]), "r"(a[2]), "r"(a[3]), "r"(b0), "r"(b1));
}
__device__ __forceinline__ void cp_async16(uint32_t smem_dst, const void* gmem_src) {
    asm volatile("cp.async.cg.shared.global [%0], [%1], 16;" :: "r"(smem_dst), "l"(gmem_src) : "memory");
}
#define CP_COMMIT() asm volatile("cp.async.commit_group;" ::: "memory")
#define CP_WAIT(n)  asm volatile("cp.async.wait_group %0;" :: "n"(n) : "memory")

__device__ __forceinline__ void cvt_store4(float4 v, char* smem, uint32_t off) {
    __half h0 = __float2half_rn(v.x), h1 = __float2half_rn(v.y);
    __half h2 = __float2half_rn(v.z), h3 = __float2half_rn(v.w);
    uint2 u;
    u.x = ((uint32_t)__half_as_ushort(h1) << 16) | __half_as_ushort(h0);
    u.y = ((uint32_t)__half_as_ushort(h3) << 16) | __half_as_ushort(h2);
    *(uint2*)(smem + off) = u;
}

// ---------------- K1: HMMA Ce GEMM (fp16, TM=256 per block) ----------------
__global__ void __launch_bounds__(256, 2)
k_main(const float* __restrict__ e, const float* __restrict__ Cb) {
    extern __shared__ char sm[];
    uint32_t smb = smem_u32(sm);
    int tid = threadIdx.x;
    int wid = tid >> 5, lane = tid & 31;

    int blk = blockIdx.x;         // == bi = b*V + i
    int b   = blk >> 8;
    size_t rbase0 = (size_t)blk * 256;

    // c2 = Cb + Bh[bi]
    if (tid < HH)
        ((float*)(sm + SM_C2))[tid] = Cb[tid] + g_lin[(size_t)3 * ROWS_H * HH + (size_t)blk * HH + tid];

    // Both B chunk tiles, once per block
    for (int i = tid; i < 2 * TILE_B / 16; i += 256)
        cp_async16(smb + SM_BW0 + i * 16, g_bt + i * 16);
    CP_COMMIT();

    int wm = wid >> 1, wn = wid & 1;     // 4 x 2 warp grid, warp tile 32x64
    uint32_t aLaneOff = (uint32_t)(wm * 32 + (lane & 15)) * (LDC * 2) + (lane >> 4) * 16;
    uint32_t bLaneOff = (uint32_t)(wn * 64 + (((lane >> 4) & 1) * 8) + (lane & 7)) * (LDC * 2)
                      + ((lane >> 3) & 1) * 16;

#pragma unroll
    for (int t = 0; t < 2; t++) {
        size_t rbase = rbase0 + t * 128;
        float d[2][8][4];
#pragma unroll
        for (int mt = 0; mt < 2; mt++)
#pragma unroll
            for (int nt = 0; nt < 8; nt++)
#pragma unroll
                for (int q = 0; q < 4; q++) d[mt][nt][q] = 0.f;

#pragma unroll
        for (int ch = 0; ch < 2; ch++) {
            // load + convert A (128 rows x 64 K) — direct LDG
            const float* eb = e + rbase * HH + ch * 64;
            for (int idx = tid; idx < 128 * 16; idx += 256) {
                int row = idx >> 4, c4 = idx & 15;
                uint32_t off = (uint32_t)row * (LDC * 2) + c4 * 8;
                float4 ev = *(const float4*)&eb[(size_t)row * HH + c4 * 4];
                cvt_store4(ev, sm, SM_AHI + off);
            }
            if (t == 0 && ch == 0) { CP_WAIT(0); }
            __syncthreads();

            uint32_t aBase = smb + SM_AHI + aLaneOff;
            uint32_t bBase = smb + (ch ? SM_BW1 : SM_BW0) + bLaneOff;
#pragma unroll
            for (int kk = 0; kk < 4; kk++) {
                uint32_t bb[16];
#pragma unroll
                for (int q = 0; q < 4; q++)
                    ldmatrix_x4(bb[q * 4], bb[q * 4 + 1], bb[q * 4 + 2], bb[q * 4 + 3],
                                bBase + kk * 32 + (uint32_t)q * 16 * (LDC * 2));
                uint32_t a0[4], a1[4];
                ldmatrix_x4(a0[0], a0[1], a0[2], a0[3], aBase + kk * 32);
                ldmatrix_x4(a1[0], a1[1], a1[2], a1[3], aBase + kk * 32 + 16 * (LDC * 2));
#pragma unroll
                for (int nt = 0; nt < 8; nt++) {
                    uint32_t b0 = bb[(nt >> 1) * 4 + (nt & 1) * 2];
                    uint32_t b1 = bb[(nt >> 1) * 4 + (nt & 1) * 2 + 1];
                    mma16816(d[0][nt], a0, b0, b1);
                    mma16816(d[1][nt], a1, b0, b1);
                }
            }
            __syncthreads();   // A tile consumed; next chunk may overwrite
        }

        // -------- fragment-direct epilogue for this tile --------
        {
            int g = lane >> 2, t2 = (lane & 3) * 2;
            const float* c2s = (const float*)(sm + SM_C2);
            const float* ahB = g_lin + (size_t)2 * ROWS_H * HH + (size_t)(b * VV + t * 128) * HH;
            const float* vhB = g_lin + (size_t)1 * ROWS_H * HH + (size_t)(b * VV + t * 128) * HH;
            float* enB = g_enew + rbase * HH;
            float* redS = (float*)(sm + SM_RED);
            float* redQ = redS + 512;
            float* redA = redQ + 512;

#pragma unroll
            for (int nt = 0; nt < 8; nt++) {
                int c = wn * 64 + nt * 8 + t2;
                float c2a = c2s[c], c2b = c2s[c + 1];
                float pS0 = 0.f, pS1 = 0.f, pQ0 = 0.f, pQ1 = 0.f, pA0 = 0.f, pA1 = 0.f;
#pragma unroll
                for (int mt = 0; mt < 2; mt++) {
#pragma unroll
                    for (int h = 0; h < 2; h++) {
                        int r = wm * 32 + mt * 16 + h * 8 + g;
                        float2 ahv = *(const float2*)&ahB[(size_t)r * HH + c];
                        float2 vhv = *(const float2*)&vhB[(size_t)r * HH + c];
                        float x0 = d[mt][nt][h * 2 + 0] + c2a + ahv.x;
                        float x1 = d[mt][nt][h * 2 + 1] + c2b + ahv.y;
                        *(float2*)&enB[(size_t)r * HH + c] = make_float2(x0, x1);
                        pS0 += x0; pS1 += x1;
                        pQ0 = fmaf(x0, x0, pQ0); pQ1 = fmaf(x1, x1, pQ1);
                        pA0 = fmaf(vhv.x, 1.f / (1.f + __expf(-x0)), pA0);
                        pA1 = fmaf(vhv.y, 1.f / (1.f + __expf(-x1)), pA1);
                    }
                }
#pragma unroll
                for (int m = 4; m <= 16; m <<= 1) {
                    pS0 += __shfl_xor_sync(0xffffffffu, pS0, m);
                    pS1 += __shfl_xor_sync(0xffffffffu, pS1, m);
                    pQ0 += __shfl_xor_sync(0xffffffffu, pQ0, m);
                    pQ1 += __shfl_xor_sync(0xffffffffu, pQ1, m);
                    pA0 += __shfl_xor_sync(0xffffffffu, pA0, m);
                    pA1 += __shfl_xor_sync(0xffffffffu, pA1, m);
                }
                if (g == 0) {
                    redS[wm * 128 + c] = pS0; redS[wm * 128 + c + 1] = pS1;
                    redQ[wm * 128 + c] = pQ0; redQ[wm * 128 + c + 1] = pQ1;
                    redA[wm * 128 + c] = pA0; redA[wm * 128 + c + 1] = pA1;
                }
            }
        }
        __syncthreads();
        if (tid < HH) {
            float* redS = (float*)(sm + SM_RED);
            float* redQ = redS + 512;
            float* redA = redQ + 512;
            float S = 0.f, Q = 0.f, A = 0.f;
#pragma unroll
            for (int w = 0; w < 4; w++) {
                S += redS[w * 128 + tid];
                Q += redQ[w * 128 + tid];
                A += redA[w * 128 + tid];
            }
            int rowblk = blk * 2 + t;
            g_statS[(size_t)tid * NBLK2 + rowblk] = S;
            g_statQ[(size_t)tid * NBLK2 + rowblk] = Q;
            g_aggp[(size_t)tid * NBLK2 + rowblk]  = A;
        }
        // red not rewritten until after ≥2 barriers in next tile's MMA phases — safe
    }
}

// ---------------- K0: four small linears + Cw pre-convert (y==4) ----------------
constexpr int WS_STRIDE = 132;
constexpr int SMEM_LIN = (HH * WS_STRIDE + 64 * HH) * 4;

__device__ __forceinline__ void fma2(unsigned long long& d, unsigned long long a, unsigned long long b) {
    asm("fma.rn.f32x2 %0, %1, %2, %0;" : "+l"(d) : "l"(a), "l"(b));
}
__device__ __forceinline__ float2 unpack2(unsigned long long v) {
    float2 r; asm("mov.b64 {%0,%1}, %2;" : "=f"(r.x), "=f"(r.y) : "l"(v)); return r;
}

__global__ void k_lin(const float* __restrict__ h,
                      const float* __restrict__ W0, const float* __restrict__ b0,
                      const float* __restrict__ W1, const float* __restrict__ b1,
                      const float* __restrict__ W2, const float* __restrict__ b2,
                      const float* __restrict__ W3, const float* __restrict__ b3,
                      const float* __restrict__ Cw) {
    if (blockIdx.y == 4) {
        int ch = blockIdx.x & 1;
        if (blockIdx.x >= 2) return;
        char* dst = g_bt + (size_t)ch * TILE_B;
        const float* wb = Cw + ch * 64;
        for (int idx = threadIdx.x; idx < 128 * 16; idx += 256) {
            int row = idx >> 4, c4 = idx & 15;
            uint32_t off = (uint32_t)row * (LDC * 2) + c4 * 8;
            float4 wv = *(const float4*)&wb[(size_t)row * HH + c4 * 4];
            cvt_store4(wv, dst, off);
        }
        return;
    }
    extern __shared__ float smf[];
    float* Ws = smf;
    float* As = Ws + HH * WS_STRIDE;

    int m = blockIdx.y;
    const float* W    = (m == 0) ? W0 : (m == 1) ? W1 : (m == 2) ? W2 : W3;
    const float* bias = (m == 0) ? b0 : (m == 1) ? b1 : (m == 2) ? b2 : b3;

    int tid = threadIdx.x;
    for (int i = tid; i < HH * 32; i += 256) {
        int n = i >> 5, kc = i & 31;
        *(float4*)&Ws[n * WS_STRIDE + kc * 4] = *(const float4*)&W[n * HH + kc * 4];
    }
    int r0 = blockIdx.x * 64;
    const float4* hsrc = (const float4*)(h + (size_t)r0 * HH);
    for (int i = tid; i < 64 * 32; i += 256) ((float4*)As)[i] = hsrc[i];
    __syncthreads();

    int tr = tid >> 5, tc = tid & 31;
    int jj0 = tr * 8;
    unsigned long long acc[8][4];
#pragma unroll
    for (int jl = 0; jl < 8; jl++)
#pragma unroll
        for (int mm = 0; mm < 4; mm++) acc[jl][mm] = 0ull;
#pragma unroll 4
    for (int k = 0; k < HH; k += 4) {
        ulonglong2 w0 = *(const ulonglong2*)&Ws[(tc +  0) * WS_STRIDE + k];
        ulonglong2 w1 = *(const ulonglong2*)&Ws[(tc + 32) * WS_STRIDE + k];
        ulonglong2 w2 = *(const ulonglong2*)&Ws[(tc + 64) * WS_STRIDE + k];
        ulonglong2 w3 = *(const ulonglong2*)&Ws[(tc + 96) * WS_STRIDE + k];
#pragma unroll
        for (int jl = 0; jl < 8; jl++) {
            ulonglong2 a = *(const ulonglong2*)&As[(jj0 + jl) * HH + k];
            fma2(acc[jl][0], a.x, w0.x); fma2(acc[jl][0], a.y, w0.y);
            fma2(acc[jl][1], a.x, w1.x); fma2(acc[jl][1], a.y, w1.y);
            fma2(acc[jl][2], a.x, w2.x); fma2(acc[jl][2], a.y, w2.y);
            fma2(acc[jl][3], a.x, w3.x); fma2(acc[jl][3], a.y, w3.y);
        }
    }
    float bv[4];
#pragma unroll
    for (int mm = 0; mm < 4; mm++) bv[mm] = bias[tc + 32 * mm];
    float* dst = g_lin + (size_t)m * ROWS_H * HH;
#pragma unroll
    for (int jl = 0; jl < 8; jl++) {
        size_t row = (size_t)(r0 + jj0 + jl) * HH;
#pragma unroll
        for (int mm = 0; mm < 4; mm++) {
            float2 p = unpack2(acc[jl][mm]);
            dst[row + tc + 32 * mm] = p.x + p.y + bv[mm];
        }
    }
}

// ---------------- K2: stats reduce (fp64) + h path + h_out ----------------
__device__ __forceinline__ double blk_red(double v, double* sb) {
    int tid = threadIdx.x;
    sb[tid] = v; __syncthreads();
    for (int o = 128; o > 0; o >>= 1) {
        if (tid < o) sb[tid] += sb[tid + o];
        __syncthreads();
    }
    double r = sb[0]; __syncthreads();
    return r;
}

__global__ void k_finalize(const float* __restrict__ h_in,
                           const float* __restrict__ gamma_h, const float* __restrict__ beta_h,
                           const float* __restrict__ gamma_e, const float* __restrict__ beta_e,
                           float* __restrict__ out_h) {
    __shared__ double sb[256];
    __shared__ float sbroad[2];
    int n = blockIdx.x;
    int tid = threadIdx.x;

    double s = 0.0, q = 0.0;
    for (int p = tid; p < NBLK2; p += 256) {
        s += (double)g_statS[(size_t)n * NBLK2 + p];
        q += (double)g_statQ[(size_t)n * NBLK2 + p];
    }
    s = blk_red(s, sb);
    q = blk_red(q, sb);
    if (tid == 0) {
        double mean = s / (double)ROWS_E;
        double var  = q / (double)ROWS_E - mean * mean;
        float rstd  = (float)(1.0 / sqrt(var + (double)EPS));
        float sc    = gamma_e[n] * rstd;
        g_scaleE[n] = sc;
        g_shiftE[n] = beta_e[n] - (float)mean * sc;
    }

    double hs = 0.0, hq = 0.0;
    for (int r = tid; r < ROWS_H; r += 256) {
        const float* ap = &g_aggp[(size_t)n * NBLK2 + r * 2];
        float agg = ap[0] + ap[1];
        float hn  = g_lin[(size_t)r * HH + n] + agg;  // Uh + agg
        g_hnew[(size_t)r * HH + n] = hn;
        hs += (double)hn; hq += (double)hn * (double)hn;
    }
    hs = blk_red(hs, sb);
    hq = blk_red(hq, sb);
    if (tid == 0) {
        double mean = hs / (double)ROWS_H;
        double var  = hq / (double)ROWS_H - mean * mean;
        float rstd  = (float)(1.0 / sqrt(var + (double)EPS));
        float sc    = gamma_h[n] * rstd;
        sbroad[0]   = sc;
        sbroad[1]   = beta_h[n] - (float)mean * sc;
    }
    __syncthreads();
    float sc = sbroad[0], sh = sbroad[1];
    for (int r = tid; r < ROWS_H; r += 256) {
        float v = fmaf(g_hnew[(size_t)r * HH + n], sc, sh);
        out_h[(size_t)r * HH + n] = h_in[(size_t)r * HH + n] + fmaxf(v, 0.f);
    }
}

// ---------------- K3: e epilogue ----------------
__global__ void k_epi(const float* __restrict__ e_in, float* __restrict__ out_e) {
    int tid = threadIdx.x;
    const float4* en4 = (const float4*)g_enew;
    const float4* ei4 = (const float4*)e_in;
    const float4* sc4 = (const float4*)g_scaleE;
    const float4* sh4 = (const float4*)g_shiftE;
    float4* out4 = (float4*)out_e;
#pragma unroll
    for (int it = 0; it < 4; it++) {
        size_t f = (size_t)blockIdx.x * 1024 + it * 256 + tid;
        int c = (int)(f & 31);
        float4 sc = __ldg(&sc4[c]);
        float4 sh = __ldg(&sh4[c]);
        float4 x  = en4[f];
        float4 ei = ei4[f];
        float4 o;
        o.x = ei.x + fmaxf(fmaf(x.x, sc.x, sh.x), 0.f);
        o.y = ei.y + fmaxf(fmaf(x.y, sc.y, sh.y), 0.f);
        o.z = ei.z + fmaxf(fmaf(x.z, sc.z, sh.z), 0.f);
        o.w = ei.w + fmaxf(fmaf(x.w, sc.w, sh.w), 0.f);
        out4[f] = o;
    }
}

extern "C" void kernel_launch(void* const* d_in, const int* in_sizes, int n_in,
                              void* d_out, int out_size) {
    (void)in_sizes; (void)n_in; (void)out_size;
    const float* h  = (const float*)d_in[0];
    const float* e  = (const float*)d_in[1];
    const float* Uw = (const float*)d_in[3];
    const float* Ub = (const float*)d_in[4];
    const float* Vw = (const float*)d_in[5];
    const float* Vb = (const float*)d_in[6];
    const float* Aw = (const float*)d_in[7];
    const float* Ab = (const float*)d_in[8];
    const float* Bw = (const float*)d_in[9];
    const float* Bb = (const float*)d_in[10];
    const float* Cw = (const float*)d_in[11];
    const float* Cb = (const float*)d_in[12];
    const float* gh = (const float*)d_in[13];
    const float* bh = (const float*)d_in[14];
    const float* ge = (const float*)d_in[15];
    const float* be = (const float*)d_in[16];
    float* out = (float*)d_out;   // [h_out (131072) | e_out (33554432)]

    cudaFuncSetAttribute(k_lin,  cudaFuncAttributeMaxDynamicSharedMemorySize, SMEM_LIN);
    cudaFuncSetAttribute(k_main, cudaFuncAttributeMaxDynamicSharedMemorySize, SM_TOTAL);

    k_lin<<<dim3(ROWS_H / 64, 5), 256, SMEM_LIN>>>(h, Uw, Ub, Vw, Vb, Aw, Ab, Bw, Bb, Cw);
    k_main<<<GRID_MAIN, 256, SM_TOTAL>>>(e, Cb);
    k_finalize<<<HH, 256>>>(h, gh, bh, ge, be, out);
    k_epi<<<ROWS_E * HH / 4096, 256>>>(e, out + ROWS_H * HH);
}